// round 7
// baseline (speedup 1.0000x reference)
#include <cuda_runtime.h>
#include <math.h>
#include <float.h>

#define B_   128
#define H_   512
#define E_   256
#define ND_  128
#define V_   5000
#define K0_  384      // E_ + ND_

typedef unsigned long long u64;

// ---------------- persistent device state ----------------
__device__ __align__(16) float g_h0T[2][H_ * B_];   // [k][b], ping-pong
__device__ __align__(16) float g_h1T[2][H_ * B_];
__device__ __align__(16) float g_c0[H_ * B_];       // cell state [j][b]
__device__ __align__(16) float g_c1[H_ * B_];
__device__ __align__(16) float g_xnT[ND_ * B_];     // noise transposed [k][b] (static)
__device__ __align__(16) float g_cval[125 * B_];    // [p][b]
__device__ int   g_cidx[125 * B_];

__device__ __forceinline__ float sigmf(float x) { return 1.0f / (1.0f + expf(-x)); }

__device__ __forceinline__ u64 dup2(float a) {
    u64 r; asm("mov.b64 %0,{%1,%1};" : "=l"(r) : "f"(a)); return r;
}
__device__ __forceinline__ u64 pack2(float lo, float hi) {
    u64 r; asm("mov.b64 %0,{%1,%2};" : "=l"(r) : "f"(lo), "f"(hi)); return r;
}
__device__ __forceinline__ void fma2(u64& d, u64 x, u64 w) {
    asm("fma.rn.f32x2 %0,%1,%2,%0;" : "+l"(d) : "l"(x), "l"(w));
}
__device__ __forceinline__ u64 add2(u64 a, u64 b) {
    u64 r; asm("add.rn.f32x2 %0,%1,%2;" : "=l"(r) : "l"(a), "l"(b)); return r;
}
__device__ __forceinline__ void unpack2(u64 a, float& x, float& y) {
    asm("mov.b64 {%0,%1},%2;" : "=f"(x), "=f"(y) : "l"(a));
}

// ================= init =================
__global__ void k_init(const float* __restrict__ noise) {
    int i = blockIdx.x * 256 + threadIdx.x;
    if (i < H_ * B_) {
        g_h0T[0][i] = 0.f; g_h1T[0][i] = 0.f;
        g_c0[i] = 0.f;     g_c1[i] = 0.f;
    }
    if (i < ND_ * B_) {
        int k = i >> 7, b = i & 127;
        g_xnT[k * B_ + b] = noise[b * ND_ + k];
    }
}

// ================= LSTM kernels =================
// grid 128, block 512 = 16 warps = 8 kz x 2 rw. Warp: 8 rows (4 gates x 2 j) x 128 batch.
// LAYER template folds KIH and the input-source selection.

template<int LAYER>
__device__ __forceinline__ void lstm_body(
    const float* __restrict__ Wih, const float* __restrict__ Whh,
    const float* __restrict__ bih, const float* __restrict__ bhh,
    const float* __restrict__ emb,            // LAYER==0 only
    const float* __restrict__ xin,            // LAYER==1: h0_new
    const float* __restrict__ hrd,            // own-layer previous h
    float* __restrict__ hwr,                  // own-layer new h
    float* __restrict__ cst,                  // cell state
    int t)
{
    constexpr int KIH  = (LAYER == 0) ? K0_ : H_;
    constexpr int SLEN1 = KIH / 8;            // seg1 k per slab (48 or 64)
    __shared__ __align__(16) u64 sred[8][32][16];   // 32KB, two-round reduce
    __shared__ int s_tok[B_];

    const int tid = threadIdx.x, bid = blockIdx.x;
    const int lane = tid & 31, wid = tid >> 5;
    const int kz = wid >> 1, rw = wid & 1;
    const int lane4 = lane * 4;
    const int jbase = bid * 4 + rw * 2;

    // ---- fused token reduce (layer 0 only) ----
    if (LAYER == 0) {
        if (tid < B_) {
            int tok = 1;
            if (t > 0) {
                float bv = -FLT_MAX; int bi = 0x7fffffff;
                #pragma unroll 5
                for (int p = 0; p < 125; p++) {
                    float v = g_cval[p * B_ + tid];
                    int  ix = g_cidx[p * B_ + tid];
                    if (v > bv || (v == bv && ix < bi)) { bv = v; bi = ix; }
                }
                tok = bi;
            }
            s_tok[tid] = tok;
        }
        __syncthreads();
    }

    u64 acc[16];
    #pragma unroll
    for (int a = 0; a < 16; a++) acc[a] = 0ull;

    const float* wbase = Wih + (size_t)jbase * KIH;

#define FMA8(WB, KK)                                                        \
    _Pragma("unroll")                                                       \
    for (int g = 0; g < 4; g++) {                                           \
        _Pragma("unroll")                                                   \
        for (int jj = 0; jj < 2; jj++) {                                    \
            int r = g * 2 + jj;                                             \
            float4 wv = *(const float4*)((WB) + (size_t)(g * H_ + jj) * KIH + (KK)); \
            u64 wa = dup2(wv.x), wb = dup2(wv.y), wc = dup2(wv.z), wd = dup2(wv.w);  \
            fma2(acc[r*2], xq0.x, wa); fma2(acc[r*2+1], xq0.y, wa);         \
            fma2(acc[r*2], xq1.x, wb); fma2(acc[r*2+1], xq1.y, wb);         \
            fma2(acc[r*2], xq2.x, wc); fma2(acc[r*2+1], xq2.y, wc);         \
            fma2(acc[r*2], xq3.x, wd); fma2(acc[r*2+1], xq3.y, wd);         \
        }                                                                   \
    }

    // ---- segment 1: x input ----
    if (LAYER == 0) {
        const float* e0 = emb + (size_t)s_tok[lane4 + 0] * E_;
        const float* e1 = emb + (size_t)s_tok[lane4 + 1] * E_;
        const float* e2 = emb + (size_t)s_tok[lane4 + 2] * E_;
        const float* e3 = emb + (size_t)s_tok[lane4 + 3] * E_;
        const int k0 = kz * SLEN1;
        #pragma unroll
        for (int ko = 0; ko < SLEN1; ko += 4) {
            const int k = k0 + ko;
            ulonglong2 xq0, xq1, xq2, xq3;
            if (k < E_) {
                float4 f0 = *(const float4*)(e0 + k);
                float4 f1 = *(const float4*)(e1 + k);
                float4 f2 = *(const float4*)(e2 + k);
                float4 f3 = *(const float4*)(e3 + k);
                xq0.x = pack2(f0.x, f1.x); xq0.y = pack2(f2.x, f3.x);
                xq1.x = pack2(f0.y, f1.y); xq1.y = pack2(f2.y, f3.y);
                xq2.x = pack2(f0.z, f1.z); xq2.y = pack2(f2.z, f3.z);
                xq3.x = pack2(f0.w, f1.w); xq3.y = pack2(f2.w, f3.w);
            } else {
                const float* nb = g_xnT + (size_t)(k - E_) * B_ + lane4;
                xq0 = *(const ulonglong2*)(nb + 0 * B_);
                xq1 = *(const ulonglong2*)(nb + 1 * B_);
                xq2 = *(const ulonglong2*)(nb + 2 * B_);
                xq3 = *(const ulonglong2*)(nb + 3 * B_);
            }
            FMA8(wbase, k);
        }
    } else {
        const int k0 = kz * SLEN1;
        #pragma unroll 4
        for (int k = k0; k < k0 + SLEN1; k += 4) {
            ulonglong2 xq0 = *(const ulonglong2*)(xin + (size_t)(k + 0) * B_ + lane4);
            ulonglong2 xq1 = *(const ulonglong2*)(xin + (size_t)(k + 1) * B_ + lane4);
            ulonglong2 xq2 = *(const ulonglong2*)(xin + (size_t)(k + 2) * B_ + lane4);
            ulonglong2 xq3 = *(const ulonglong2*)(xin + (size_t)(k + 3) * B_ + lane4);
            FMA8(wbase, k);
        }
    }

    // ---- segment 2: recurrent (KIH_r = H_) ----
    {
        const float* wbase2 = Whh + (size_t)jbase * H_;
        const int k0 = kz * (H_ / 8);
        #pragma unroll 4
        for (int k = k0; k < k0 + H_ / 8; k += 4) {
            ulonglong2 xq0 = *(const ulonglong2*)(hrd + (size_t)(k + 0) * B_ + lane4);
            ulonglong2 xq1 = *(const ulonglong2*)(hrd + (size_t)(k + 1) * B_ + lane4);
            ulonglong2 xq2 = *(const ulonglong2*)(hrd + (size_t)(k + 2) * B_ + lane4);
            ulonglong2 xq3 = *(const ulonglong2*)(hrd + (size_t)(k + 3) * B_ + lane4);
            // inline FMA8 with KIH=H_ weight stride
            #pragma unroll
            for (int g = 0; g < 4; g++) {
                #pragma unroll
                for (int jj = 0; jj < 2; jj++) {
                    int r = g * 2 + jj;
                    float4 wv = *(const float4*)(wbase2 + (size_t)(g * H_ + jj) * H_ + k);
                    u64 wa = dup2(wv.x), wb = dup2(wv.y), wc = dup2(wv.z), wd = dup2(wv.w);
                    fma2(acc[r*2], xq0.x, wa); fma2(acc[r*2+1], xq0.y, wa);
                    fma2(acc[r*2], xq1.x, wb); fma2(acc[r*2+1], xq1.y, wb);
                    fma2(acc[r*2], xq2.x, wc); fma2(acc[r*2+1], xq2.y, wc);
                    fma2(acc[r*2], xq3.x, wd); fma2(acc[r*2+1], xq3.y, wd);
                }
            }
        }
    }
#undef FMA8

    // ---- two-round cross-slab reduction (8 kz -> 1) ----
    if (kz >= 4) {
        #pragma unroll
        for (int a = 0; a < 16; a++) sred[(kz - 4) * 2 + rw][lane][a] = acc[a];
    }
    __syncthreads();
    if (kz < 4) {
        #pragma unroll
        for (int a = 0; a < 16; a++) acc[a] = add2(acc[a], sred[kz * 2 + rw][lane][a]);
    }
    __syncthreads();
    if (kz >= 1 && kz < 4) {
        #pragma unroll
        for (int a = 0; a < 16; a++) sred[(kz - 1) * 2 + rw][lane][a] = acc[a];
    }
    __syncthreads();
    if (kz == 0) {
        #pragma unroll
        for (int s = 0; s < 3; s++)
            #pragma unroll
            for (int a = 0; a < 16; a++)
                acc[a] = add2(acc[a], sred[s * 2 + rw][lane][a]);

        #pragma unroll
        for (int jj = 0; jj < 2; jj++) {
            int j = jbase + jj;
            float gv[4][4];
            #pragma unroll
            for (int g = 0; g < 4; g++) {
                unpack2(acc[(g*2+jj)*2 + 0], gv[g][0], gv[g][1]);
                unpack2(acc[(g*2+jj)*2 + 1], gv[g][2], gv[g][3]);
            }
            float bsum[4];
            #pragma unroll
            for (int g = 0; g < 4; g++) bsum[g] = bih[g * H_ + j] + bhh[g * H_ + j];
            float4 c4 = *(float4*)&cst[j * B_ + lane4];
            float cc[4] = {c4.x, c4.y, c4.z, c4.w};
            float hh[4];
            #pragma unroll
            for (int i = 0; i < 4; i++) {
                float iv = sigmf(gv[0][i] + bsum[0]);
                float fv = sigmf(gv[1][i] + bsum[1]);
                float gg = tanhf(gv[2][i] + bsum[2]);
                float ov = sigmf(gv[3][i] + bsum[3]);
                float cn = fv * cc[i] + iv * gg;
                cc[i] = cn;
                hh[i] = ov * tanhf(cn);
            }
            *(float4*)&cst[j * B_ + lane4] = make_float4(cc[0], cc[1], cc[2], cc[3]);
            *(float4*)&hwr[j * B_ + lane4] = make_float4(hh[0], hh[1], hh[2], hh[3]);
        }
    }
}

__global__ void __launch_bounds__(512) k_lstm0(
    const float* __restrict__ emb,
    const float* __restrict__ Wih, const float* __restrict__ Whh,
    const float* __restrict__ bih, const float* __restrict__ bhh, int t)
{
    lstm_body<0>(Wih, Whh, bih, bhh, emb, nullptr,
                 g_h0T[t & 1], g_h0T[(t + 1) & 1], g_c0, t);
}

__global__ void __launch_bounds__(512) k_lstm1(
    const float* __restrict__ Wih, const float* __restrict__ Whh,
    const float* __restrict__ bih, const float* __restrict__ bhh, int t)
{
    lstm_body<1>(Wih, Whh, bih, bhh, nullptr, g_h0T[(t + 1) & 1],
                 g_h1T[t & 1], g_h1T[(t + 1) & 1], g_c1, t);
}

// ================= logits + partial argmax =================
// grid 125, block 512 = 16 warps = 2 kz x 8 rw. Warp: 5 vocab rows x 128 batch.
__global__ void __launch_bounds__(512, 1) k_logits(
    const float* __restrict__ Wout, const float* __restrict__ bout,
    float* __restrict__ out, int t, int T)
{
    __shared__ u64   sred[8][32][10];
    __shared__ float s_cv[8][B_];
    __shared__ int   s_ci[8][B_];

    const int tid = threadIdx.x, lane = tid & 31, wid = tid >> 5;
    const int kz = wid >> 3, rw = wid & 7;
    const int lane4 = lane * 4;
    const int cbase = blockIdx.x * 40 + rw * 5;

    const float* h1 = g_h1T[(t + 1) & 1];
    const float* w0 = Wout + (size_t)(cbase + 0) * H_;
    const float* w1 = Wout + (size_t)(cbase + 1) * H_;
    const float* w2 = Wout + (size_t)(cbase + 2) * H_;
    const float* w3 = Wout + (size_t)(cbase + 3) * H_;
    const float* w4 = Wout + (size_t)(cbase + 4) * H_;

    u64 acc[10];
    #pragma unroll
    for (int a = 0; a < 10; a++) acc[a] = 0ull;

#define ROWF(WP, AI) do {                                              \
    float4 wv_ = *(const float4*)((WP) + k);                           \
    u64 wa_ = dup2(wv_.x), wb_ = dup2(wv_.y),                          \
        wc_ = dup2(wv_.z), wd_ = dup2(wv_.w);                          \
    fma2(acc[(AI)*2+0], xq0.x, wa_); fma2(acc[(AI)*2+1], xq0.y, wa_);  \
    fma2(acc[(AI)*2+0], xq1.x, wb_); fma2(acc[(AI)*2+1], xq1.y, wb_);  \
    fma2(acc[(AI)*2+0], xq2.x, wc_); fma2(acc[(AI)*2+1], xq2.y, wc_);  \
    fma2(acc[(AI)*2+0], xq3.x, wd_); fma2(acc[(AI)*2+1], xq3.y, wd_);  \
} while (0)

    {
        #pragma unroll 2
        for (int k = kz * 256; k < kz * 256 + 256; k += 4) {
            ulonglong2 xq0 = *(const ulonglong2*)(h1 + (size_t)(k+0)*B_ + lane4);
            ulonglong2 xq1 = *(const ulonglong2*)(h1 + (size_t)(k+1)*B_ + lane4);
            ulonglong2 xq2 = *(const ulonglong2*)(h1 + (size_t)(k+2)*B_ + lane4);
            ulonglong2 xq3 = *(const ulonglong2*)(h1 + (size_t)(k+3)*B_ + lane4);
            ROWF(w0,0); ROWF(w1,1); ROWF(w2,2); ROWF(w3,3); ROWF(w4,4);
        }
    }
#undef ROWF

    if (kz == 1) {
        #pragma unroll
        for (int a = 0; a < 10; a++) sred[rw][lane][a] = acc[a];
    }
    __syncthreads();
    if (kz == 0) {
        #pragma unroll
        for (int a = 0; a < 10; a++) acc[a] = add2(acc[a], sred[rw][lane][a]);

        float vals[5][4];
        #pragma unroll
        for (int q = 0; q < 5; q++) {
            float bq = bout[cbase + q];
            float v0, v1, v2, v3;
            unpack2(acc[q*2+0], v0, v1);
            unpack2(acc[q*2+1], v2, v3);
            vals[q][0] = v0 + bq; vals[q][1] = v1 + bq;
            vals[q][2] = v2 + bq; vals[q][3] = v3 + bq;
        }
        #pragma unroll
        for (int i = 0; i < 4; i++) {
            int b = lane4 + i;
            float* op = out + ((size_t)b * T + t) * V_ + cbase;
            float bv = -FLT_MAX; int bix = 0;
            #pragma unroll
            for (int q = 0; q < 5; q++) {
                float v = vals[q][i];
                op[q] = v;
                if (v > bv) { bv = v; bix = cbase + q; }   // first max on ties
            }
            s_cv[rw][b] = bv;
            s_ci[rw][b] = bix;
        }
    }
    __syncthreads();
    if (tid < B_) {
        int b = tid;
        float bv = -FLT_MAX; int bi = 0x7fffffff;
        #pragma unroll
        for (int p = 0; p < 8; p++) {
            float v = s_cv[p][b]; int ix = s_ci[p][b];
            if (v > bv || (v == bv && ix < bi)) { bv = v; bi = ix; }
        }
        g_cval[blockIdx.x * B_ + b] = bv;
        g_cidx[blockIdx.x * B_ + b] = bi;
    }
}

// ================= final heads =================
__global__ void k_head(const float* __restrict__ Watt, const float* __restrict__ batt,
                       const float* __restrict__ Wsoph, const float* __restrict__ bsoph,
                       float* __restrict__ out, int T)
{
    const float* h1 = g_h1T[T & 1];
    int m = blockIdx.x;          // 0..23
    int b = threadIdx.x;         // 0..127
    size_t base = (size_t)B_ * T * V_;
    const float* w; float bias; float* op;
    if (m < 8) {
        w = Watt + m * H_; bias = batt[m];
        op = out + base + (size_t)b * 8 + m;
    } else {
        int mm = m - 8;
        w = Wsoph + mm * H_; bias = bsoph[mm];
        op = out + base + (size_t)B_ * 8 + (size_t)b * 16 + mm;
    }
    float a = 0.f;
    #pragma unroll 4
    for (int k = 0; k < H_; k += 4) {
        float4 wv = *(const float4*)(w + k);
        a += h1[(k + 0) * B_ + b] * wv.x + h1[(k + 1) * B_ + b] * wv.y
           + h1[(k + 2) * B_ + b] * wv.z + h1[(k + 3) * B_ + b] * wv.w;
    }
    *op = a + bias;
}

// ================= launch =================
extern "C" void kernel_launch(void* const* d_in, const int* in_sizes, int n_in,
                              void* d_out, int out_size)
{
    const float* noise = (const float*)d_in[0];
    const float* emb   = (const float*)d_in[1];
    const float* Wih0  = (const float*)d_in[2];
    const float* Whh0  = (const float*)d_in[3];
    const float* bih0  = (const float*)d_in[4];
    const float* bhh0  = (const float*)d_in[5];
    const float* Wih1  = (const float*)d_in[6];
    const float* Whh1  = (const float*)d_in[7];
    const float* bih1  = (const float*)d_in[8];
    const float* bhh1  = (const float*)d_in[9];
    const float* Wout  = (const float*)d_in[10];
    const float* bout  = (const float*)d_in[11];
    const float* Watt  = (const float*)d_in[12];
    const float* batt  = (const float*)d_in[13];
    const float* Wsoph = (const float*)d_in[14];
    const float* bsoph = (const float*)d_in[15];
    float* out = (float*)d_out;

    int T = (out_size - B_ * 24) / (B_ * V_);
    if (T <= 0) T = 200;

    k_init<<<256, 256>>>(noise);
    for (int t = 0; t < T; t++) {
        k_lstm0<<<128, 512>>>(emb, Wih0, Whh0, bih0, bhh0, t);
        k_lstm1<<<128, 512>>>(Wih1, Whh1, bih1, bhh1, t);
        k_logits<<<125, 512>>>(Wout, bout, out, t, T);
    }
    k_head<<<24, 128>>>(Watt, batt, Wsoph, bsoph, out, T);
}